// round 8
// baseline (speedup 1.0000x reference)
#include <cuda_runtime.h>
#include <math.h>

#define NPIX 16384
#define EDIM 128
#define FDIM 512

typedef unsigned long long u64;

// ---------------- scratch (static, no allocation) ----------------
__device__ float g_xn  [NPIX*EDIM];   // LN1 output, NHWC
__device__ float g_xres[NPIX*EDIM];   // x in NHWC (residual)
__device__ float g_qkv [NPIX*384];    // q|k|v per pixel
__device__ float g_z0  [NPIX*EDIM];   // attention output, NHWC
__device__ float g_t   [4*EDIM*EDIM]; // per-batch bilinear matrix
__device__ float g_z2  [NPIX*EDIM];   // bilinear + residual
__device__ float g_z3  [NPIX*EDIM];   // LN2 output
__device__ float g_h1  [NPIX*FDIM];   // FFN hidden

// ---------------- f32x2 helpers ----------------
__device__ __forceinline__ u64 pk2(float lo, float hi) {
    u64 r; asm("mov.b64 %0, {%1, %2};" : "=l"(r) : "f"(lo), "f"(hi)); return r;
}
__device__ __forceinline__ void fma2(u64 &d, u64 a, u64 b) {
    asm("fma.rn.f32x2 %0, %1, %2, %0;" : "+l"(d) : "l"(a), "l"(b));
}
__device__ __forceinline__ float2 upk2(u64 v) {
    float2 r; asm("mov.b64 {%0, %1}, %2;" : "=f"(r.x), "=f"(r.y) : "l"(v)); return r;
}

// ---------------- warp reductions ----------------
__device__ __forceinline__ float warp_sum(float v) {
    v += __shfl_xor_sync(0xffffffffu, v, 16);
    v += __shfl_xor_sync(0xffffffffu, v, 8);
    v += __shfl_xor_sync(0xffffffffu, v, 4);
    v += __shfl_xor_sync(0xffffffffu, v, 2);
    v += __shfl_xor_sync(0xffffffffu, v, 1);
    return v;
}

// ---------------- LN1: x NCHW -> xn, xres NHWC (tiled, coalesced) ----------------
// Block handles 64 pixels. Stage [64 pixels][128 ch] in smem (pixel-major, pad 132).
__global__ __launch_bounds__(256) void ln1_kernel(const float* __restrict__ x,
                                                  const float* __restrict__ g,
                                                  const float* __restrict__ b) {
    __shared__ float T[64*132];
    int tid = threadIdx.x;
    int p0  = blockIdx.x * 64;        // first pixel of tile
    int n   = p0 >> 12;
    int yx0 = p0 & 4095;
    const float* base = x + (size_t)n * EDIM * 4096 + yx0;
    // coalesced load: for fixed c, 64 consecutive pixels
#pragma unroll 8
    for (int i = tid; i < 64*EDIM; i += 256) {
        int c = i >> 6, p = i & 63;
        T[p*132 + c] = base[(size_t)c*4096 + p];
    }
    __syncthreads();
    int wid = tid >> 5, lane = tid & 31;
#pragma unroll
    for (int k = 0; k < 8; ++k) {
        int p = wid*8 + k;
        float4 v = *(const float4*)(T + p*132 + lane*4);   // addr4 = p*33+lane: conflict-free
        float s  = v.x + v.y + v.z + v.w;
        float ss = v.x*v.x + v.y*v.y + v.z*v.z + v.w*v.w;
        s = warp_sum(s); ss = warp_sum(ss);
        float mean = s * (1.f/128.f);
        float var  = ss * (1.f/128.f) - mean*mean;
        float rstd = rsqrtf(var + 1e-5f);
        int c = lane*4;
        float4 o;
        o.x = (v.x-mean)*rstd*g[c+0] + b[c+0];
        o.y = (v.y-mean)*rstd*g[c+1] + b[c+1];
        o.z = (v.z-mean)*rstd*g[c+2] + b[c+2];
        o.w = (v.w-mean)*rstd*g[c+3] + b[c+3];
        *(float4*)(g_xn   + (size_t)(p0+p)*EDIM + c) = o;
        *(float4*)(g_xres + (size_t)(p0+p)*EDIM + c) = v;
    }
}

// ---------------- LN2: z2 NHWC -> z3 NHWC ----------------
__global__ void ln2_kernel(const float* __restrict__ g,
                           const float* __restrict__ b) {
    int gw   = (blockIdx.x * blockDim.x + threadIdx.x) >> 5;
    int lane = threadIdx.x & 31;
    if (gw >= NPIX) return;
    float4 v = *(const float4*)(g_z2 + (size_t)gw*EDIM + lane*4);
    float s  = v.x + v.y + v.z + v.w;
    float ss = v.x*v.x + v.y*v.y + v.z*v.z + v.w*v.w;
    s = warp_sum(s); ss = warp_sum(ss);
    float mean = s * (1.f/128.f);
    float var  = ss * (1.f/128.f) - mean*mean;
    float rstd = rsqrtf(var + 1e-5f);
    int c = lane*4;
    float4 o;
    o.x = (v.x-mean)*rstd*g[c+0] + b[c+0];
    o.y = (v.y-mean)*rstd*g[c+1] + b[c+1];
    o.z = (v.z-mean)*rstd*g[c+2] + b[c+2];
    o.w = (v.w-mean)*rstd*g[c+3] + b[c+3];
    *(float4*)(g_z3 + (size_t)gw*EDIM + c) = o;
}

// ================= GEMM core: C[128x128] = A[128xK] * B[128xK]^T =================
// 256 threads, 8x8 microtile (4+4 split), f32x2 FMAs, double-buffered smem.
#define GK 16      // k-chunk
#define GPAD 132   // floats per smem row

__device__ __forceinline__ void gemm128(const float* __restrict__ A,
                                        const float* __restrict__ B,
                                        int K, float C[8][8],
                                        float* __restrict__ As,
                                        float* __restrict__ Bs) {
    const int tid = threadIdx.x;
    const int row = tid >> 1;            // 0..127 (load row)
    const int kb  = (tid & 1) * 8;       // k-offset 0 or 8 within chunk
    const int tm  = tid & 15;
    const int tn  = tid >> 4;

    u64 acc[4][8];
#pragma unroll
    for (int p = 0; p < 4; ++p)
#pragma unroll
        for (int n = 0; n < 8; ++n) acc[p][n] = 0ull;

    const int niter = K >> 4;
    const int so = kb*GPAD + row;        // store offset within buffer
    // iter-0 prefetch + store to buffer 0
    float4 pa0 = *(const float4*)(A + (size_t)row*K + kb);
    float4 pa1 = *(const float4*)(A + (size_t)row*K + kb + 4);
    float4 pb0 = *(const float4*)(B + (size_t)row*K + kb);
    float4 pb1 = *(const float4*)(B + (size_t)row*K + kb + 4);
    As[so+0*GPAD]=pa0.x; As[so+1*GPAD]=pa0.y; As[so+2*GPAD]=pa0.z; As[so+3*GPAD]=pa0.w;
    As[so+4*GPAD]=pa1.x; As[so+5*GPAD]=pa1.y; As[so+6*GPAD]=pa1.z; As[so+7*GPAD]=pa1.w;
    Bs[so+0*GPAD]=pb0.x; Bs[so+1*GPAD]=pb0.y; Bs[so+2*GPAD]=pb0.z; Bs[so+3*GPAD]=pb0.w;
    Bs[so+4*GPAD]=pb1.x; Bs[so+5*GPAD]=pb1.y; Bs[so+6*GPAD]=pb1.z; Bs[so+7*GPAD]=pb1.w;
    __syncthreads();

    for (int it = 0; it < niter; ++it) {
        const int cb = (it & 1) * (GK*GPAD);        // compute buffer
        const int nb = ((it & 1) ^ 1) * (GK*GPAD);  // next buffer
        const bool more = (it + 1 < niter);
        if (more) {   // issue global loads early; consumed after compute
            const float* An = A + (size_t)row*K + (it+1)*GK + kb;
            const float* Bn = B + (size_t)row*K + (it+1)*GK + kb;
            pa0 = *(const float4*)(An);
            pa1 = *(const float4*)(An + 4);
            pb0 = *(const float4*)(Bn);
            pb1 = *(const float4*)(Bn + 4);
        }
#pragma unroll
        for (int kk = 0; kk < GK; ++kk) {
            const float* ar = As + cb + kk*GPAD;
            const float* br = Bs + cb + kk*GPAD;
            float4 av0 = *(const float4*)(ar + tm*4);
            float4 av1 = *(const float4*)(ar + 64 + tm*4);
            float4 bv0 = *(const float4*)(br + tn*4);
            float4 bv1 = *(const float4*)(br + 64 + tn*4);
            u64 ap[4];
            ap[0] = pk2(av0.x, av0.y); ap[1] = pk2(av0.z, av0.w);
            ap[2] = pk2(av1.x, av1.y); ap[3] = pk2(av1.z, av1.w);
            u64 bd[8];
            bd[0] = pk2(bv0.x, bv0.x); bd[1] = pk2(bv0.y, bv0.y);
            bd[2] = pk2(bv0.z, bv0.z); bd[3] = pk2(bv0.w, bv0.w);
            bd[4] = pk2(bv1.x, bv1.x); bd[5] = pk2(bv1.y, bv1.y);
            bd[6] = pk2(bv1.z, bv1.z); bd[7] = pk2(bv1.w, bv1.w);
#pragma unroll
            for (int p = 0; p < 4; ++p)
#pragma unroll
                for (int n = 0; n < 8; ++n)
                    fma2(acc[p][n], ap[p], bd[n]);
        }
        if (more) {
            As[nb+so+0*GPAD]=pa0.x; As[nb+so+1*GPAD]=pa0.y; As[nb+so+2*GPAD]=pa0.z; As[nb+so+3*GPAD]=pa0.w;
            As[nb+so+4*GPAD]=pa1.x; As[nb+so+5*GPAD]=pa1.y; As[nb+so+6*GPAD]=pa1.z; As[nb+so+7*GPAD]=pa1.w;
            Bs[nb+so+0*GPAD]=pb0.x; Bs[nb+so+1*GPAD]=pb0.y; Bs[nb+so+2*GPAD]=pb0.z; Bs[nb+so+3*GPAD]=pb0.w;
            Bs[nb+so+4*GPAD]=pb1.x; Bs[nb+so+5*GPAD]=pb1.y; Bs[nb+so+6*GPAD]=pb1.z; Bs[nb+so+7*GPAD]=pb1.w;
        }
        __syncthreads();
    }
#pragma unroll
    for (int p = 0; p < 4; ++p) {
        int r = (p >> 1)*4 + (p & 1)*2;
#pragma unroll
        for (int n = 0; n < 8; ++n) {
            float2 f = upk2(acc[p][n]);
            C[r+0][n] = f.x;
            C[r+1][n] = f.y;
        }
    }
}

__device__ __forceinline__ int loc_m(int tm, int r) { return (r < 4) ? tm*4 + r : 64 + tm*4 + (r-4); }
__device__ __forceinline__ int loc_n(int tn, int n) { return (n < 4) ? tn*4 + n : 64 + tn*4 + (n-4); }

// ---------------- QKV ----------------
__global__ __launch_bounds__(256, 2) void gemm_qkv_kernel(
        const float* __restrict__ wq, const float* __restrict__ wk,
        const float* __restrict__ wv, const float* __restrict__ bq,
        const float* __restrict__ bk, const float* __restrict__ bv) {
    __shared__ float As[2*GK*GPAD], Bs[2*GK*GPAD];
    float C[8][8];
    int by = blockIdx.x;
    int bx = blockIdx.y;
    const float* W    = (bx == 0) ? wq : (bx == 1 ? wk : wv);
    const float* bias = (bx == 0) ? bq : (bx == 1 ? bk : bv);
    gemm128(g_xn + (size_t)by*128*EDIM, W, EDIM, C, As, Bs);
    int tm = threadIdx.x & 15, tn = threadIdx.x >> 4;
#pragma unroll
    for (int r = 0; r < 8; ++r) {
        int p = by*128 + loc_m(tm, r);
#pragma unroll
        for (int half = 0; half < 2; ++half) {
            int c0 = half*64 + tn*4;
            float4 o;
            o.x = C[r][half*4+0] + bias[c0+0];
            o.y = C[r][half*4+1] + bias[c0+1];
            o.z = C[r][half*4+2] + bias[c0+2];
            o.w = C[r][half*4+3] + bias[c0+3];
            *(float4*)(g_qkv + (size_t)p*384 + bx*128 + c0) = o;
        }
    }
}

// ---------------- bilinear t ----------------
__global__ void bil_t_kernel(const float* __restrict__ bil_w,
                             const float* __restrict__ qcoeff) {
    int i = blockIdx.x * blockDim.x + threadIdx.x;
    if (i >= 4*EDIM*EDIM) return;
    int n  = i >> 14;
    int oi = i & 16383;
    const float4* wp = (const float4*)(bil_w + (size_t)oi*64);
    const float4* qp = (const float4*)(qcoeff + (size_t)n*64);
    float s = 0.f;
#pragma unroll
    for (int q = 0; q < 16; ++q) {
        float4 a = wp[q], b = qp[q];
        s += a.x*b.x + a.y*b.y + a.z*b.z + a.w*b.w;
    }
    g_t[(size_t)n*16384 + oi] = s;
}

// ---------------- attention: 8x8 tile, channel-split two-pass, 53KB smem ----------------
#define HALO 14
#define HROWQ 17   // float4 per halo row (16 data + 1 pad)

__global__ __launch_bounds__(256, 2) void attn_kernel(const float* __restrict__ rel_bias) {
    extern __shared__ float4 S4[];           // 196 * 17 * 16B = 53312 B
    __shared__ float s_rb[196];
    int bid = blockIdx.x;
    int n  = bid >> 6;
    int ty = (bid >> 3) & 7;
    int tx = bid & 7;
    int tid  = threadIdx.x;
    int py   = tid >> 5;          // warp id = tile row
    int lane = tid & 31;
    int h    = lane >> 3;         // head
    int px   = lane & 7;          // tile col
    int pix  = ((n*64) + ty*8 + py)*64 + tx*8 + px;

    float4 q[8];
    const float4* qp = (const float4*)(g_qkv + (size_t)pix*384 + h*32);
#pragma unroll
    for (int d = 0; d < 8; ++d) q[d] = qp[d];

    if (tid < 196) s_rb[tid] = rel_bias[tid];

    const int y0 = ty*8 - 3, x0 = tx*8 - 3;
    const float4* qkv4 = (const float4*)g_qkv;   // 96 float4 per pixel

    float sc[49];
    __syncthreads();   // s_rb visible
#pragma unroll
    for (int i = 0; i < 49; ++i) sc[i] = s_rb[h*49 + i];

    // ---- scores: two channel-half passes over K ----
#pragma unroll
    for (int pass = 0; pass < 2; ++pass) {
        for (int i = tid; i < 196*16; i += 256) {
            int r = i >> 4, c = i & 15;            // c: head=c>>2, d=c&3
            int hy = r / HALO, hx = r - hy*HALO;
            int gy = y0 + hy, gx = x0 + hx;
            float4 v = make_float4(0.f, 0.f, 0.f, 0.f);
            if ((unsigned)gy < 64u && (unsigned)gx < 64u)
                v = qkv4[(size_t)((n*64 + gy)*64 + gx)*96 + 32 + (c>>2)*8 + pass*4 + (c&3)];
            S4[r*HROWQ + c] = v;
        }
        __syncthreads();
        for (int iy = 0; iy < 7; ++iy) {
            int rbase = (py + iy)*HALO + px;
#pragma unroll
            for (int ix = 0; ix < 7; ++ix) {
                const float4* kp = S4 + (rbase + ix)*HROWQ + h*4;
                float s0 = 0.f, s1 = 0.f, s2 = 0.f, s3 = 0.f;
                {
                    float4 k0 = kp[0], k1 = kp[1], k2 = kp[2], k3 = kp[3];
                    float4 q0 = q[pass*4+0], q1 = q[pass*4+1], q2 = q[pass*4+2], q3 = q[pass*4+3];
                    s0 = q0.x*k0.x + q0.y*k0.y + q0.z*k0.z + q0.w*k0.w;
                    s1 = q1.x*k1.x + q1.y*k1.y + q1.z*k1.z + q1.w*k1.w;
                    s2 = q2.x*k2.x + q2.y*k2.y + q2.z*k2.z + q2.w*k2.w;
                    s3 = q3.x*k3.x + q3.y*k3.y + q3.z*k3.z + q3.w*k3.w;
                }
                sc[iy*7 + ix] += (s0 + s1) + (s2 + s3);
            }
        }
        __syncthreads();   // done reading before next pass overwrites
    }

    // ---- thread-private softmax over 49 ----
    float m = sc[0];
#pragma unroll
    for (int i = 1; i < 49; ++i) m = fmaxf(m, sc[i]);
    float sum = 0.f;
#pragma unroll
    for (int i = 0; i < 49; ++i) { sc[i] = __expf(sc[i] - m); sum += sc[i]; }
    float inv = 1.f / sum;
#pragma unroll
    for (int i = 0; i < 49; ++i) sc[i] *= inv;

    // ---- attn @ V: two channel-half passes ----
    float4 acc[8];
#pragma unroll
    for (int d = 0; d < 8; ++d) acc[d] = make_float4(0.f, 0.f, 0.f, 0.f);
#pragma unroll
    for (int pass = 0; pass < 2; ++pass) {
        for (int i = tid; i < 196*16; i += 256) {
            int r = i >> 4, c = i & 15;
            int hy = r / HALO, hx = r - hy*HALO;
            int gy = y0 + hy, gx = x0 + hx;
            float4 v = make_float4(0.f, 0.f, 0.f, 0.f);
            if ((unsigned)gy < 64u && (unsigned)gx < 64u)
                v = qkv4[(size_t)((n*64 + gy)*64 + gx)*96 + 64 + (c>>2)*8 + pass*4 + (c&3)];
            S4[r*HROWQ + c] = v;
        }
        __syncthreads();
        for (int iy = 0; iy < 7; ++iy) {
            int rbase = (py + iy)*HALO + px;
#pragma unroll
            for (int ix = 0; ix < 7; ++ix) {
                float w = sc[iy*7 + ix];
                const float4* vp = S4 + (rbase + ix)*HROWQ + h*4;
#pragma unroll
                for (int d = 0; d < 4; ++d) {
                    float4 v = vp[d];
                    acc[pass*4+d].x += w*v.x; acc[pass*4+d].y += w*v.y;
                    acc[pass*4+d].z += w*v.z; acc[pass*4+d].w += w*v.w;
                }
            }
        }
        __syncthreads();
    }
    float4* op = (float4*)(g_z0 + (size_t)pix*EDIM + h*32);
#pragma unroll
    for (int d = 0; d < 8; ++d) op[d] = acc[d];
}

// ---------------- z2 = z0 @ t[n]^T + bil_b + xres ----------------
__global__ __launch_bounds__(256, 2) void gemm_z1_kernel(const float* __restrict__ bil_b) {
    __shared__ float As[2*GK*GPAD], Bs[2*GK*GPAD];
    float C[8][8];
    int by = blockIdx.x;
    int n  = blockIdx.y;
    gemm128(g_z0 + ((size_t)n*4096 + by*128)*EDIM,
            g_t + (size_t)n*EDIM*EDIM, EDIM, C, As, Bs);
    int tm = threadIdx.x & 15, tn = threadIdx.x >> 4;
#pragma unroll
    for (int r = 0; r < 8; ++r) {
        int p = n*4096 + by*128 + loc_m(tm, r);
#pragma unroll
        for (int half = 0; half < 2; ++half) {
            int c0 = half*64 + tn*4;
            float4 xr = *(const float4*)(g_xres + (size_t)p*EDIM + c0);
            float4 o;
            o.x = C[r][half*4+0] + bil_b[c0+0] + xr.x;
            o.y = C[r][half*4+1] + bil_b[c0+1] + xr.y;
            o.z = C[r][half*4+2] + bil_b[c0+2] + xr.z;
            o.w = C[r][half*4+3] + bil_b[c0+3] + xr.w;
            *(float4*)(g_z2 + (size_t)p*EDIM + c0) = o;
        }
    }
}

// ---------------- FFN1: h1 = gelu(z3 @ w1^T + b1) ----------------
__global__ __launch_bounds__(256, 2) void gemm_ffn1_kernel(const float* __restrict__ w1,
                                                           const float* __restrict__ b1) {
    __shared__ float As[2*GK*GPAD], Bs[2*GK*GPAD];
    float C[8][8];
    int by = blockIdx.x;
    int bx = blockIdx.y;
    gemm128(g_z3 + (size_t)by*128*EDIM, w1 + (size_t)bx*128*EDIM, EDIM, C, As, Bs);
    int tm = threadIdx.x & 15, tn = threadIdx.x >> 4;
#pragma unroll
    for (int r = 0; r < 8; ++r) {
        int p = by*128 + loc_m(tm, r);
#pragma unroll
        for (int half = 0; half < 2; ++half) {
            int c0 = half*64 + tn*4;
            float4 o;
#pragma unroll
            for (int j = 0; j < 4; ++j) {
                float v = C[r][half*4+j] + b1[bx*128 + c0 + j];
                ((float*)&o)[j] = 0.5f * v * (1.0f + erff(v * 0.70710678118654752f));
            }
            *(float4*)(g_h1 + (size_t)p*FDIM + bx*128 + c0) = o;
        }
    }
}

// ---------------- FFN2: out(NCHW) = h1 @ w2^T + b2 + z2 ----------------
__global__ __launch_bounds__(256, 2) void gemm_ffn2_kernel(const float* __restrict__ w2,
                                                           const float* __restrict__ b2,
                                                           float* __restrict__ out) {
    __shared__ float As[2*GK*GPAD], Bs[2*GK*GPAD];
    float C[8][8];
    int by = blockIdx.x;
    gemm128(g_h1 + (size_t)by*128*FDIM, w2, FDIM, C, As, Bs);
    int tm = threadIdx.x & 15, tn = threadIdx.x >> 4;
#pragma unroll
    for (int n8 = 0; n8 < 8; ++n8) {
        int oc = loc_n(tn, n8);
#pragma unroll
        for (int blk = 0; blk < 2; ++blk) {
            int p0 = by*128 + blk*64 + tm*4;
            int n  = p0 >> 12;
            int yx = p0 & 4095;
            float4 o;
#pragma unroll
            for (int i = 0; i < 4; ++i) {
                int r = blk*4 + i;
                int p = p0 + i;
                ((float*)&o)[i] = C[r][n8] + b2[oc] + g_z2[(size_t)p*EDIM + oc];
            }
            *(float4*)(out + ((size_t)n*EDIM + oc)*4096 + yx) = o;
        }
    }
}

// ---------------- launch ----------------
extern "C" void kernel_launch(void* const* d_in, const int* in_sizes, int n_in,
                              void* d_out, int out_size) {
    const float* x        = (const float*)d_in[0];
    const float* qcoeff   = (const float*)d_in[1];
    const float* wq       = (const float*)d_in[2];
    const float* bq       = (const float*)d_in[3];
    const float* wk       = (const float*)d_in[4];
    const float* bk       = (const float*)d_in[5];
    const float* wv       = (const float*)d_in[6];
    const float* bv       = (const float*)d_in[7];
    const float* rel_bias = (const float*)d_in[8];
    const float* ln1_g    = (const float*)d_in[9];
    const float* ln1_b    = (const float*)d_in[10];
    const float* bil_w    = (const float*)d_in[11];
    const float* bil_b    = (const float*)d_in[12];
    const float* ln2_g    = (const float*)d_in[13];
    const float* ln2_b    = (const float*)d_in[14];
    const float* w1       = (const float*)d_in[15];
    const float* b1       = (const float*)d_in[16];
    const float* w2       = (const float*)d_in[17];
    const float* b2       = (const float*)d_in[18];
    float* out = (float*)d_out;

    const int attn_smem = 196 * HROWQ * (int)sizeof(float4);  // 53312 B
    cudaFuncSetAttribute(attn_kernel, cudaFuncAttributeMaxDynamicSharedMemorySize, attn_smem);

    ln1_kernel      <<<NPIX/64, 256>>>(x, ln1_g, ln1_b);
    gemm_qkv_kernel <<<dim3(128, 3), 256>>>(wq, wk, wv, bq, bk, bv);
    bil_t_kernel    <<<256, 256>>>(bil_w, qcoeff);
    attn_kernel     <<<256, 256, attn_smem>>>(rel_bias);
    gemm_z1_kernel  <<<dim3(32, 4), 256>>>(bil_b);
    ln2_kernel      <<<NPIX/8, 256>>>(ln2_g, ln2_b);
    gemm_ffn1_kernel<<<dim3(128, 4), 256>>>(w1, b1);
    gemm_ffn2_kernel<<<128, 256>>>(w2, b2, out);
}

// round 9
// speedup vs baseline: 1.0224x; 1.0224x over previous
#include <cuda_runtime.h>
#include <math.h>

#define NPIX 16384
#define EDIM 128
#define FDIM 512

typedef unsigned long long u64;

// ---------------- scratch (static, no allocation) ----------------
__device__ float g_xn  [NPIX*EDIM];   // LN1 output, NHWC
__device__ float g_xres[NPIX*EDIM];   // x in NHWC (residual)
__device__ float g_qkv [NPIX*384];    // q|k|v per pixel
__device__ float g_z0  [NPIX*EDIM];   // attention output, NHWC
__device__ float g_t   [4*EDIM*EDIM]; // per-batch bilinear matrix
__device__ float g_z2  [NPIX*EDIM];   // bilinear + residual
__device__ float g_z3  [NPIX*EDIM];   // LN2 output
__device__ float g_h1  [NPIX*FDIM];   // FFN hidden

// ---------------- f32x2 helpers ----------------
__device__ __forceinline__ u64 pk2(float lo, float hi) {
    u64 r; asm("mov.b64 %0, {%1, %2};" : "=l"(r) : "f"(lo), "f"(hi)); return r;
}
__device__ __forceinline__ void fma2(u64 &d, u64 a, u64 b) {
    asm("fma.rn.f32x2 %0, %1, %2, %0;" : "+l"(d) : "l"(a), "l"(b));
}
__device__ __forceinline__ float2 upk2(u64 v) {
    float2 r; asm("mov.b64 {%0, %1}, %2;" : "=f"(r.x), "=f"(r.y) : "l"(v)); return r;
}

// ---------------- warp reductions ----------------
__device__ __forceinline__ float warp_sum(float v) {
    v += __shfl_xor_sync(0xffffffffu, v, 16);
    v += __shfl_xor_sync(0xffffffffu, v, 8);
    v += __shfl_xor_sync(0xffffffffu, v, 4);
    v += __shfl_xor_sync(0xffffffffu, v, 2);
    v += __shfl_xor_sync(0xffffffffu, v, 1);
    return v;
}

// ---------------- LN1: x NCHW -> xn, xres NHWC (tiled, pad 136) ----------------
#define LPAD 136
__global__ __launch_bounds__(256) void ln1_kernel(const float* __restrict__ x,
                                                  const float* __restrict__ g,
                                                  const float* __restrict__ b) {
    __shared__ float T[64*LPAD];
    int tid = threadIdx.x;
    int p0  = blockIdx.x * 64;        // first pixel of tile
    int n   = p0 >> 12;
    int yx0 = p0 & 4095;
    const float* base = x + (size_t)n * EDIM * 4096 + yx0;
    // coalesced: for fixed c, 64 consecutive pixels; smem stores 4-way conflicted (pad 136)
#pragma unroll 8
    for (int i = tid; i < 64*EDIM; i += 256) {
        int c = i >> 6, p = i & 63;
        T[p*LPAD + c] = base[(size_t)c*4096 + p];
    }
    __syncthreads();
    int wid = tid >> 5, lane = tid & 31;
#pragma unroll
    for (int k = 0; k < 8; ++k) {
        int p = wid*8 + k;
        float4 v = *(const float4*)(T + p*LPAD + lane*4);   // addr4 = p*34+lane: conflict-free
        float s  = v.x + v.y + v.z + v.w;
        float ss = v.x*v.x + v.y*v.y + v.z*v.z + v.w*v.w;
        s = warp_sum(s); ss = warp_sum(ss);
        float mean = s * (1.f/128.f);
        float var  = ss * (1.f/128.f) - mean*mean;
        float rstd = rsqrtf(var + 1e-5f);
        int c = lane*4;
        float4 o;
        o.x = (v.x-mean)*rstd*g[c+0] + b[c+0];
        o.y = (v.y-mean)*rstd*g[c+1] + b[c+1];
        o.z = (v.z-mean)*rstd*g[c+2] + b[c+2];
        o.w = (v.w-mean)*rstd*g[c+3] + b[c+3];
        *(float4*)(g_xn   + (size_t)(p0+p)*EDIM + c) = o;
        *(float4*)(g_xres + (size_t)(p0+p)*EDIM + c) = v;
    }
}

// ================= GEMM core (R5): C[128x128] = A[128xK]*B[128xK]^T, f32x2 =================
#define GK 16      // k-chunk
#define GPAD 132   // floats per smem row

__device__ __forceinline__ void gemm128(const float* __restrict__ A,
                                        const float* __restrict__ B,
                                        int K, float C[8][8],
                                        float* __restrict__ As,
                                        float* __restrict__ Bs) {
    const int tid = threadIdx.x;
    const int row = tid >> 1;            // 0..127 (load row)
    const int kb  = (tid & 1) * 8;       // k-offset 0 or 8 within chunk
    const int tm  = tid & 15;
    const int tn  = tid >> 4;

    u64 acc[4][8];
#pragma unroll
    for (int p = 0; p < 4; ++p)
#pragma unroll
        for (int n = 0; n < 8; ++n) acc[p][n] = 0ull;

    const int niter = K >> 4;
    float4 pa0 = *(const float4*)(A + (size_t)row*K + kb);
    float4 pa1 = *(const float4*)(A + (size_t)row*K + kb + 4);
    float4 pb0 = *(const float4*)(B + (size_t)row*K + kb);
    float4 pb1 = *(const float4*)(B + (size_t)row*K + kb + 4);

    for (int it = 0; it < niter; ++it) {
        __syncthreads();
        As[(kb+0)*GPAD + row] = pa0.x;
        As[(kb+1)*GPAD + row] = pa0.y;
        As[(kb+2)*GPAD + row] = pa0.z;
        As[(kb+3)*GPAD + row] = pa0.w;
        As[(kb+4)*GPAD + row] = pa1.x;
        As[(kb+5)*GPAD + row] = pa1.y;
        As[(kb+6)*GPAD + row] = pa1.z;
        As[(kb+7)*GPAD + row] = pa1.w;
        Bs[(kb+0)*GPAD + row] = pb0.x;
        Bs[(kb+1)*GPAD + row] = pb0.y;
        Bs[(kb+2)*GPAD + row] = pb0.z;
        Bs[(kb+3)*GPAD + row] = pb0.w;
        Bs[(kb+4)*GPAD + row] = pb1.x;
        Bs[(kb+5)*GPAD + row] = pb1.y;
        Bs[(kb+6)*GPAD + row] = pb1.z;
        Bs[(kb+7)*GPAD + row] = pb1.w;
        __syncthreads();
        if (it + 1 < niter) {
            const float* An = A + (size_t)row*K + (it+1)*GK + kb;
            const float* Bn = B + (size_t)row*K + (it+1)*GK + kb;
            pa0 = *(const float4*)(An);
            pa1 = *(const float4*)(An + 4);
            pb0 = *(const float4*)(Bn);
            pb1 = *(const float4*)(Bn + 4);
        }
#pragma unroll
        for (int kk = 0; kk < GK; ++kk) {
            const float* ar = As + kk*GPAD;
            const float* br = Bs + kk*GPAD;
            float4 av0 = *(const float4*)(ar + tm*4);
            float4 av1 = *(const float4*)(ar + 64 + tm*4);
            float4 bv0 = *(const float4*)(br + tn*4);
            float4 bv1 = *(const float4*)(br + 64 + tn*4);
            u64 ap[4];
            ap[0] = pk2(av0.x, av0.y); ap[1] = pk2(av0.z, av0.w);
            ap[2] = pk2(av1.x, av1.y); ap[3] = pk2(av1.z, av1.w);
            u64 bd[8];
            bd[0] = pk2(bv0.x, bv0.x); bd[1] = pk2(bv0.y, bv0.y);
            bd[2] = pk2(bv0.z, bv0.z); bd[3] = pk2(bv0.w, bv0.w);
            bd[4] = pk2(bv1.x, bv1.x); bd[5] = pk2(bv1.y, bv1.y);
            bd[6] = pk2(bv1.z, bv1.z); bd[7] = pk2(bv1.w, bv1.w);
#pragma unroll
            for (int p = 0; p < 4; ++p)
#pragma unroll
                for (int n = 0; n < 8; ++n)
                    fma2(acc[p][n], ap[p], bd[n]);
        }
    }
#pragma unroll
    for (int p = 0; p < 4; ++p) {
        int r = (p >> 1)*4 + (p & 1)*2;
#pragma unroll
        for (int n = 0; n < 8; ++n) {
            float2 f = upk2(acc[p][n]);
            C[r+0][n] = f.x;
            C[r+1][n] = f.y;
        }
    }
}

__device__ __forceinline__ int loc_m(int tm, int r) { return (r < 4) ? tm*4 + r : 64 + tm*4 + (r-4); }
__device__ __forceinline__ int loc_n(int tn, int n) { return (n < 4) ? tn*4 + n : 64 + tn*4 + (n-4); }

// ---------------- QKV ----------------
__global__ __launch_bounds__(256, 2) void gemm_qkv_kernel(
        const float* __restrict__ wq, const float* __restrict__ wk,
        const float* __restrict__ wv, const float* __restrict__ bq,
        const float* __restrict__ bk, const float* __restrict__ bv) {
    __shared__ float As[GK*GPAD], Bs[GK*GPAD];
    float C[8][8];
    int by = blockIdx.x;
    int bx = blockIdx.y;
    const float* W    = (bx == 0) ? wq : (bx == 1 ? wk : wv);
    const float* bias = (bx == 0) ? bq : (bx == 1 ? bk : bv);
    gemm128(g_xn + (size_t)by*128*EDIM, W, EDIM, C, As, Bs);
    int tm = threadIdx.x & 15, tn = threadIdx.x >> 4;
#pragma unroll
    for (int r = 0; r < 8; ++r) {
        int p = by*128 + loc_m(tm, r);
#pragma unroll
        for (int half = 0; half < 2; ++half) {
            int c0 = half*64 + tn*4;
            float4 o;
            o.x = C[r][half*4+0] + bias[c0+0];
            o.y = C[r][half*4+1] + bias[c0+1];
            o.z = C[r][half*4+2] + bias[c0+2];
            o.w = C[r][half*4+3] + bias[c0+3];
            *(float4*)(g_qkv + (size_t)p*384 + bx*128 + c0) = o;
        }
    }
}

// ---------------- bilinear t ----------------
__global__ void bil_t_kernel(const float* __restrict__ bil_w,
                             const float* __restrict__ qcoeff) {
    int i = blockIdx.x * blockDim.x + threadIdx.x;
    if (i >= 4*EDIM*EDIM) return;
    int n  = i >> 14;
    int oi = i & 16383;
    const float4* wp = (const float4*)(bil_w + (size_t)oi*64);
    const float4* qp = (const float4*)(qcoeff + (size_t)n*64);
    float s = 0.f;
#pragma unroll
    for (int q = 0; q < 16; ++q) {
        float4 a = wp[q], b = qp[q];
        s += a.x*b.x + a.y*b.y + a.z*b.z + a.w*b.w;
    }
    g_t[(size_t)n*16384 + oi] = s;
}

// ---------------- attention: R4 full-channel tiled version ----------------
#define HALO 14
#define HROW 33   // float4 units per halo row (32 data + 1 pad)

__global__ __launch_bounds__(256, 2) void attn_kernel(const float* __restrict__ rel_bias) {
    extern __shared__ float4 S4[];           // 196 * 33 float4 = 103488 B
    __shared__ float s_rb[196];
    int bid = blockIdx.x;
    int n  = bid >> 6;
    int ty = (bid >> 3) & 7;
    int tx = bid & 7;
    int tid  = threadIdx.x;
    int py   = tid >> 5;          // warp id = tile row
    int lane = tid & 31;
    int h    = lane >> 3;         // head
    int px   = lane & 7;          // tile col
    int pix  = ((n*64) + ty*8 + py)*64 + tx*8 + px;

    float4 q[8];
    const float4* qp = (const float4*)(g_qkv + (size_t)pix*384 + h*32);
#pragma unroll
    for (int d = 0; d < 8; ++d) q[d] = qp[d];

    if (tid < 196) s_rb[tid] = rel_bias[tid];

    const int y0 = ty*8 - 3, x0 = tx*8 - 3;
    for (int i = tid; i < 196*32; i += 256) {
        int r = i >> 5, c = i & 31;
        int hy = r / HALO, hx = r - hy*HALO;
        int gy = y0 + hy, gx = x0 + hx;
        float4 v = make_float4(0.f, 0.f, 0.f, 0.f);
        if ((unsigned)gy < 64u && (unsigned)gx < 64u)
            v = *(const float4*)(g_qkv + (size_t)((n*64 + gy)*64 + gx)*384 + 128 + c*4);
        S4[r*HROW + c] = v;
    }
    __syncthreads();

    float sc[49];
    for (int iy = 0; iy < 7; ++iy) {
        int rbase = (py + iy)*HALO + px;
#pragma unroll
        for (int ix = 0; ix < 7; ++ix) {
            const float4* kp = S4 + (rbase + ix)*HROW + h*8;
            float s = 0.f;
#pragma unroll
            for (int d = 0; d < 8; ++d) {
                float4 k = kp[d];
                s += q[d].x*k.x + q[d].y*k.y + q[d].z*k.z + q[d].w*k.w;
            }
            sc[iy*7 + ix] = s + s_rb[h*49 + iy*7 + ix];
        }
    }

    float m = sc[0];
#pragma unroll
    for (int i = 1; i < 49; ++i) m = fmaxf(m, sc[i]);
    float sum = 0.f;
#pragma unroll
    for (int i = 0; i < 49; ++i) { sc[i] = __expf(sc[i] - m); sum += sc[i]; }
    float inv = 1.f / sum;
#pragma unroll
    for (int i = 0; i < 49; ++i) sc[i] *= inv;

    __syncthreads();

    for (int i = tid; i < 196*32; i += 256) {
        int r = i >> 5, c = i & 31;
        int hy = r / HALO, hx = r - hy*HALO;
        int gy = y0 + hy, gx = x0 + hx;
        float4 v = make_float4(0.f, 0.f, 0.f, 0.f);
        if ((unsigned)gy < 64u && (unsigned)gx < 64u)
            v = *(const float4*)(g_qkv + (size_t)((n*64 + gy)*64 + gx)*384 + 256 + c*4);
        S4[r*HROW + c] = v;
    }
    __syncthreads();

    float4 acc[8];
#pragma unroll
    for (int d = 0; d < 8; ++d) acc[d] = make_float4(0.f, 0.f, 0.f, 0.f);
    for (int iy = 0; iy < 7; ++iy) {
        int rbase = (py + iy)*HALO + px;
#pragma unroll
        for (int ix = 0; ix < 7; ++ix) {
            float w = sc[iy*7 + ix];
            const float4* vp = S4 + (rbase + ix)*HROW + h*8;
#pragma unroll
            for (int d = 0; d < 8; ++d) {
                float4 v = vp[d];
                acc[d].x += w*v.x; acc[d].y += w*v.y;
                acc[d].z += w*v.z; acc[d].w += w*v.w;
            }
        }
    }
    float4* op = (float4*)(g_z0 + (size_t)pix*EDIM + h*32);
#pragma unroll
    for (int d = 0; d < 8; ++d) op[d] = acc[d];
}

// ---------------- z1 + residual + fused LN2: writes g_z2 AND g_z3 ----------------
__global__ __launch_bounds__(256, 2) void gemm_z1_ln2_kernel(const float* __restrict__ bil_b,
                                                             const float* __restrict__ ln2g,
                                                             const float* __restrict__ ln2b) {
    __shared__ float As[GK*GPAD], Bs[GK*GPAD];
    __shared__ float rsum[128*17], rssq[128*17];
    __shared__ float rmean[128], rrstd[128];
    float C[8][8];
    int by = blockIdx.x;  // 0..31 within batch
    int n  = blockIdx.y;  // 0..3
    gemm128(g_z0 + ((size_t)n*4096 + by*128)*EDIM,
            g_t + (size_t)n*EDIM*EDIM, EDIM, C, As, Bs);
    int tm = threadIdx.x & 15, tn = threadIdx.x >> 4;
    // add bias + residual; accumulate row partials; write z2
    float psum[8], pssq[8];
#pragma unroll
    for (int r = 0; r < 8; ++r) {
        int p = n*4096 + by*128 + loc_m(tm, r);
        float s = 0.f, ss = 0.f;
#pragma unroll
        for (int half = 0; half < 2; ++half) {
            int c0 = half*64 + tn*4;
            float4 xr = *(const float4*)(g_xres + (size_t)p*EDIM + c0);
            float4 o;
            o.x = C[r][half*4+0] + bil_b[c0+0] + xr.x;
            o.y = C[r][half*4+1] + bil_b[c0+1] + xr.y;
            o.z = C[r][half*4+2] + bil_b[c0+2] + xr.z;
            o.w = C[r][half*4+3] + bil_b[c0+3] + xr.w;
            C[r][half*4+0] = o.x; C[r][half*4+1] = o.y;
            C[r][half*4+2] = o.z; C[r][half*4+3] = o.w;
            s  += o.x + o.y + o.z + o.w;
            ss += o.x*o.x + o.y*o.y + o.z*o.z + o.w*o.w;
            *(float4*)(g_z2 + (size_t)p*EDIM + c0) = o;
        }
        psum[r] = s; pssq[r] = ss;
    }
#pragma unroll
    for (int r = 0; r < 8; ++r) {
        int lm = loc_m(tm, r);
        rsum[lm*17 + tn] = psum[r];
        rssq[lm*17 + tn] = pssq[r];
    }
    __syncthreads();
    int tid = threadIdx.x;
    if (tid < 128) {
        float s = 0.f, ss = 0.f;
#pragma unroll
        for (int j = 0; j < 16; ++j) { s += rsum[tid*17 + j]; ss += rssq[tid*17 + j]; }
        float mean = s * (1.f/128.f);
        float var  = ss * (1.f/128.f) - mean*mean;
        rmean[tid] = mean;
        rrstd[tid] = rsqrtf(var + 1e-5f);
    }
    __syncthreads();
#pragma unroll
    for (int r = 0; r < 8; ++r) {
        int lm = loc_m(tm, r);
        int p  = n*4096 + by*128 + lm;
        float mean = rmean[lm], rstd = rrstd[lm];
#pragma unroll
        for (int half = 0; half < 2; ++half) {
            int c0 = half*64 + tn*4;
            float4 o;
            o.x = (C[r][half*4+0]-mean)*rstd*ln2g[c0+0] + ln2b[c0+0];
            o.y = (C[r][half*4+1]-mean)*rstd*ln2g[c0+1] + ln2b[c0+1];
            o.z = (C[r][half*4+2]-mean)*rstd*ln2g[c0+2] + ln2b[c0+2];
            o.w = (C[r][half*4+3]-mean)*rstd*ln2g[c0+3] + ln2b[c0+3];
            *(float4*)(g_z3 + (size_t)p*EDIM + c0) = o;
        }
    }
}

// ---------------- FFN1: h1 = gelu(z3 @ w1^T + b1) ----------------
__global__ __launch_bounds__(256, 2) void gemm_ffn1_kernel(const float* __restrict__ w1,
                                                           const float* __restrict__ b1) {
    __shared__ float As[GK*GPAD], Bs[GK*GPAD];
    float C[8][8];
    int by = blockIdx.x;
    int bx = blockIdx.y;
    gemm128(g_z3 + (size_t)by*128*EDIM, w1 + (size_t)bx*128*EDIM, EDIM, C, As, Bs);
    int tm = threadIdx.x & 15, tn = threadIdx.x >> 4;
#pragma unroll
    for (int r = 0; r < 8; ++r) {
        int p = by*128 + loc_m(tm, r);
#pragma unroll
        for (int half = 0; half < 2; ++half) {
            int c0 = half*64 + tn*4;
            float4 o;
#pragma unroll
            for (int j = 0; j < 4; ++j) {
                float v = C[r][half*4+j] + b1[bx*128 + c0 + j];
                ((float*)&o)[j] = 0.5f * v * (1.0f + erff(v * 0.70710678118654752f));
            }
            *(float4*)(g_h1 + (size_t)p*FDIM + bx*128 + c0) = o;
        }
    }
}

// ---------------- FFN2: out(NCHW) = h1 @ w2^T + b2 + z2 ----------------
__global__ __launch_bounds__(256, 2) void gemm_ffn2_kernel(const float* __restrict__ w2,
                                                           const float* __restrict__ b2,
                                                           float* __restrict__ out) {
    __shared__ float As[GK*GPAD], Bs[GK*GPAD];
    float C[8][8];
    int by = blockIdx.x;
    gemm128(g_h1 + (size_t)by*128*FDIM, w2, FDIM, C, As, Bs);
    int tm = threadIdx.x & 15, tn = threadIdx.x >> 4;
#pragma unroll
    for (int n8 = 0; n8 < 8; ++n8) {
        int oc = loc_n(tn, n8);
#pragma unroll
        for (int blk = 0; blk < 2; ++blk) {
            int p0 = by*128 + blk*64 + tm*4;
            int n  = p0 >> 12;
            int yx = p0 & 4095;
            float4 o;
#pragma unroll
            for (int i = 0; i < 4; ++i) {
                int r = blk*4 + i;
                int p = p0 + i;
                ((float*)&o)[i] = C[r][n8] + b2[oc] + g_z2[(size_t)p*EDIM + oc];
            }
            *(float4*)(out + ((size_t)n*EDIM + oc)*4096 + yx) = o;
        }
    }
}

// ---------------- launch ----------------
extern "C" void kernel_launch(void* const* d_in, const int* in_sizes, int n_in,
                              void* d_out, int out_size) {
    const float* x        = (const float*)d_in[0];
    const float* qcoeff   = (const float*)d_in[1];
    const float* wq       = (const float*)d_in[2];
    const float* bq       = (const float*)d_in[3];
    const float* wk       = (const float*)d_in[4];
    const float* bk       = (const float*)d_in[5];
    const float* wv       = (const float*)d_in[6];
    const float* bv       = (const float*)d_in[7];
    const float* rel_bias = (const float*)d_in[8];
    const float* ln1_g    = (const float*)d_in[9];
    const float* ln1_b    = (const float*)d_in[10];
    const float* bil_w    = (const float*)d_in[11];
    const float* bil_b    = (const float*)d_in[12];
    const float* ln2_g    = (const float*)d_in[13];
    const float* ln2_b    = (const float*)d_in[14];
    const float* w1       = (const float*)d_in[15];
    const float* b1       = (const float*)d_in[16];
    const float* w2       = (const float*)d_in[17];
    const float* b2       = (const float*)d_in[18];
    float* out = (float*)d_out;

    const int attn_smem = 196 * HROW * (int)sizeof(float4);  // 103488 B
    cudaFuncSetAttribute(attn_kernel, cudaFuncAttributeMaxDynamicSharedMemorySize, attn_smem);
    cudaFuncSetAttribute(attn_kernel, cudaFuncAttributePreferredSharedMemoryCarveout, 100);

    ln1_kernel       <<<NPIX/64, 256>>>(x, ln1_g, ln1_b);
    gemm_qkv_kernel  <<<dim3(128, 3), 256>>>(wq, wk, wv, bq, bk, bv);
    bil_t_kernel     <<<256, 256>>>(bil_w, qcoeff);
    attn_kernel      <<<256, 256, attn_smem>>>(rel_bias);
    gemm_z1_ln2_kernel<<<dim3(32, 4), 256>>>(bil_b, ln2_g, ln2_b);
    gemm_ffn1_kernel <<<dim3(128, 4), 256>>>(w1, b1);
    gemm_ffn2_kernel <<<128, 256>>>(w2, b2, out);
}